// round 17
// baseline (speedup 1.0000x reference)
#include <cuda_runtime.h>
#include <cuda_fp16.h>
#include <cstdint>
#include <math.h>

// Problem constants
#define BATCH 1024
#define TT    169
#define FDYN  36
#define FSTAT 19
#define HID   128
#define MTOT  (BATCH * TT)

// ---------------------------------------------------------------------------
// Scratch (device globals)
// ---------------------------------------------------------------------------
__device__ __half g_xpre16[(size_t)MTOT * 1024];
__device__ __half g_cur0h[(size_t)MTOT * 256];
__device__ __half g_cur1h[(size_t)MTOT * 256];
__device__ float  g_sbuf[BATCH * 16];
__device__ float  g_attb[BATCH * 256];
__device__ __half g_wh16[4 * 128 * 512];   // column-REORDERED: col = (h>>3)*32 + gate*8 + (h&7)
__device__ __half g_wx0[36 * 1024];        // column-REORDERED for coalesced xpre reads
__device__ __half g_wx1[256 * 1024];
__device__ float  g_bx0[1024];
__device__ float  g_bx1[1024];

// ---------------------------------------------------------------------------
// MMA / ldmatrix / fast-math helpers
// ---------------------------------------------------------------------------
__device__ __forceinline__ unsigned smem_u32(const void* p) {
    return (unsigned)__cvta_generic_to_shared(p);
}
__device__ __forceinline__ void ldsm_x4(unsigned& r0, unsigned& r1, unsigned& r2, unsigned& r3, unsigned a) {
    asm volatile("ldmatrix.sync.aligned.m8n8.x4.shared.b16 {%0,%1,%2,%3}, [%4];"
                 : "=r"(r0), "=r"(r1), "=r"(r2), "=r"(r3) : "r"(a));
}
__device__ __forceinline__ void ldsm_x4_t(unsigned& r0, unsigned& r1, unsigned& r2, unsigned& r3, unsigned a) {
    asm volatile("ldmatrix.sync.aligned.m8n8.x4.trans.shared.b16 {%0,%1,%2,%3}, [%4];"
                 : "=r"(r0), "=r"(r1), "=r"(r2), "=r"(r3) : "r"(a));
}
__device__ __forceinline__ void mma16816(float* c, unsigned a0, unsigned a1, unsigned a2, unsigned a3,
                                         unsigned b0, unsigned b1) {
    asm volatile("mma.sync.aligned.m16n8k16.row.col.f32.f16.f16.f32 "
                 "{%0,%1,%2,%3}, {%4,%5,%6,%7}, {%8,%9}, {%0,%1,%2,%3};"
                 : "+f"(c[0]), "+f"(c[1]), "+f"(c[2]), "+f"(c[3])
                 : "r"(a0), "r"(a1), "r"(a2), "r"(a3), "r"(b0), "r"(b1));
}
__device__ __forceinline__ void cp_async16(unsigned dst, const void* src) {
    asm volatile("cp.async.cg.shared.global [%0], [%1], 16;" :: "r"(dst), "l"(src));
}
__device__ __forceinline__ float tanh_apx(float x) {
    float r; asm("tanh.approx.f32 %0, %1;" : "=f"(r) : "f"(x)); return r;
}
__device__ __forceinline__ float sig_apx(float x) {
    return fmaf(tanh_apx(0.5f * x), 0.5f, 0.5f);
}

// xpre column interleave within a direction: lane-contiguous 16B per (row, hp)
__device__ __forceinline__ int xpre_newc(int c) {
    int gate = c >> 7;
    int h = c & 127;
    return (h >> 3) * 32 + ((h & 7) >> 1) * 8 + gate * 2 + (h & 1);
}

// ---------------------------------------------------------------------------
// Weight conversion (split into two kernels so the ncu capture window
// [-s 5 -c 1] lands on gemm1 instead of rec1).
// ---------------------------------------------------------------------------
__global__ __launch_bounds__(256) void prep_wh(
    const float* __restrict__ Wh_f0, const float* __restrict__ Wh_b0,
    const float* __restrict__ Wh_f1, const float* __restrict__ Wh_b1)
{
    const int N_WH = 4 * 65536;
    for (int idx = blockIdx.x * 256 + threadIdx.x; idx < N_WH; idx += gridDim.x * 256) {
        int which = idx >> 16;
        int off = idx & 65535;
        int k = off >> 9;
        int c_orig = off & 511;
        int gate = c_orig >> 7;
        int h = c_orig & 127;
        int newc = (h >> 3) * 32 + gate * 8 + (h & 7);
        const float* src = (which == 0) ? Wh_f0 : (which == 1) ? Wh_b0 : (which == 2) ? Wh_f1 : Wh_b1;
        g_wh16[which * 65536 + k * 512 + newc] = __float2half(src[off]);
    }
}

__global__ __launch_bounds__(256) void prep_wx(
    const float* __restrict__ Wx_f0, const float* __restrict__ Wx_b0,
    const float* __restrict__ Wx_f1, const float* __restrict__ Wx_b1,
    const float* __restrict__ bb_f0, const float* __restrict__ bb_b0,
    const float* __restrict__ bb_f1, const float* __restrict__ bb_b1)
{
    const int N_W0 = 36 * 1024;
    const int N_W1 = 256 * 1024;
    const int N_ALL = N_W0 + N_W1 + 2048;
    for (int idx = blockIdx.x * 256 + threadIdx.x; idx < N_ALL; idx += gridDim.x * 256) {
        if (idx < N_W0) {
            int k = idx >> 10;
            int n = idx & 1023;
            int dirbase = (n < 512) ? 0 : 512;
            int c = n & 511;
            float v = (n < 512) ? Wx_f0[k * 512 + c] : Wx_b0[k * 512 + c];
            g_wx0[k * 1024 + dirbase + xpre_newc(c)] = __float2half(v);
        } else if (idx < N_W0 + N_W1) {
            int j = idx - N_W0;
            int k = j >> 10;
            int n = j & 1023;
            int dirbase = (n < 512) ? 0 : 512;
            int c = n & 511;
            float v = (n < 512) ? Wx_f1[k * 512 + c] : Wx_b1[k * 512 + c];
            g_wx1[k * 1024 + dirbase + xpre_newc(c)] = __float2half(v);
        } else {
            int j = idx - N_W0 - N_W1;
            int n = j & 1023;
            int dirbase = (n < 512) ? 0 : 512;
            int c = n & 511;
            if (j < 1024) {
                float v = (n < 512) ? bb_f0[c] : bb_b0[c];
                g_bx0[dirbase + xpre_newc(c)] = v;
            } else {
                float v = (n < 512) ? bb_f1[c] : bb_b1[c];
                g_bx1[dirbase + xpre_newc(c)] = v;
            }
        }
    }
}

// ---------------------------------------------------------------------------
// Static branch -> g_sbuf
// ---------------------------------------------------------------------------
__global__ __launch_bounds__(256) void static_kernel(
    const float* __restrict__ x, const float* __restrict__ w0, const float* __restrict__ b0,
    const float* __restrict__ w1, const float* __restrict__ b1)
{
    int b = blockIdx.x * blockDim.x + threadIdx.x;
    if (b >= BATCH) return;
    float xin[FSTAT];
#pragma unroll
    for (int i = 0; i < FSTAT; ++i) xin[i] = x[b * FSTAT + i];
    float h0[16];
#pragma unroll
    for (int j = 0; j < 16; ++j) {
        float a = b0[j];
#pragma unroll
        for (int i = 0; i < FSTAT; ++i) a += xin[i] * w0[i * 16 + j];
        h0[j] = fmaxf(a, 0.f);
    }
#pragma unroll
    for (int j = 0; j < 16; ++j) {
        float a = b1[j];
#pragma unroll
        for (int i = 0; i < 16; ++i) a += h0[i] * w1[i * 16 + j];
        g_sbuf[b * 16 + j] = fmaxf(a, 0.f);
    }
}

// ---------------------------------------------------------------------------
// Input-projection GEMM v3 -> g_xpre16.
// BM=128, BN=128, BK=32; 256 threads (8 warps, warp tile 32x64);
// cp.async 3-stage pipeline (ONE barrier per k-iter); inactive-row store skip.
// Dynamic smem (57KB) -> 2 CTA/SM.
// ---------------------------------------------------------------------------
#define GA_STRIDE 40
#define GB_STRIDE 136
#define GA_BUF    (128 * GA_STRIDE)           // 5120 halves per stage
#define GB_BUF    (32 * GB_STRIDE)            // 4352 halves per stage
#define G_B_HOFF  (3 * GA_BUF)                // half-index of B stage 0
#define G_ACT_OFF ((3 * GA_BUF + 3 * GB_BUF) * 2)   // byte offset of actf
#define GEMM_SMEM (G_ACT_OFF + 128)

__global__ __launch_bounds__(256) void xpre_gemm2(
    const float* __restrict__ Afloat, int K, int layer,
    const int* __restrict__ seq_len)
{
    extern __shared__ __align__(16) char gsm[];
    __half* A_sm = (__half*)gsm;
    __half* B_sm = A_sm + G_B_HOFF;
    char*   actf = gsm + G_ACT_OFF;
    __half* Stage = (__half*)gsm;             // epilogue alias

    const int m0 = blockIdx.y * 128;
    const int nb = blockIdx.x * 128;
    const int tid = threadIdx.x;

    if (tid < 128) {
        int m = m0 + tid;
        int bi = m / TT;
        int t = m - bi * TT;
        actf[tid] = (t < seq_len[bi]) ? 1 : 0;
    }
    __syncthreads();
    int anyact = (tid < 128) ? actf[tid] : 0;
    if (!__syncthreads_or(anyact)) return;

    const __half* Bw = (layer == 0) ? g_wx0 : g_wx1;
    const float* bias = (layer == 0) ? g_bx0 : g_bx1;
    const int niter = (K + 31) / 32;

    const int warp = tid >> 5;
    const int lane = tid & 31;
    const int wy = warp >> 1;
    const int wx = warp & 1;

    auto load_stage = [&](int it) {
        const int k0 = it * 32;
        __half* As = A_sm + (it % 3) * GA_BUF;
        __half* Bs = B_sm + (it % 3) * GB_BUF;
        if (layer == 1) {
#pragma unroll
            for (int j = 0; j < 2; ++j) {
                int idx = tid + j * 256;
                int row = idx >> 2;
                int colc = (idx & 3) * 8;
                cp_async16(smem_u32(&As[row * GA_STRIDE + colc]),
                           &g_cur0h[(size_t)(m0 + row) * 256 + k0 + colc]);
            }
        } else {
#pragma unroll
            for (int j = 0; j < 16; ++j) {
                int idx = tid + j * 256;
                int row = idx >> 5;
                int col = idx & 31;
                int k = k0 + col;
                __half hv = __float2half(0.f);
                if (k < K) hv = __float2half(Afloat[(size_t)(m0 + row) * K + k]);
                As[row * GA_STRIDE + col] = hv;
            }
        }
#pragma unroll
        for (int j = 0; j < 2; ++j) {
            int idx = tid + j * 256;
            int row = idx >> 4;
            int colc = (idx & 15) * 8;
            int k = k0 + row;
            if (k < K) {
                cp_async16(smem_u32(&Bs[row * GB_STRIDE + colc]),
                           &Bw[(size_t)k * 1024 + nb + colc]);
            } else {
                *(uint4*)&Bs[row * GB_STRIDE + colc] = make_uint4(0u, 0u, 0u, 0u);
            }
        }
        asm volatile("cp.async.commit_group;");
    };

    float c[2][8][4];
#pragma unroll
    for (int mr = 0; mr < 2; ++mr)
#pragma unroll
        for (int i = 0; i < 8; ++i)
#pragma unroll
            for (int j = 0; j < 4; ++j) c[mr][i][j] = 0.f;

    load_stage(0);
    if (niter > 1) load_stage(1);

    for (int it = 0; it < niter; ++it) {
        if (it + 1 < niter) {
            asm volatile("cp.async.wait_group 1;");
        } else {
            asm volatile("cp.async.wait_group 0;");
        }
        __syncthreads();

        const __half* As = A_sm + (it % 3) * GA_BUF;
        const __half* Bs = B_sm + (it % 3) * GB_BUF;
#pragma unroll
        for (int kk = 0; kk < 2; ++kk) {
            unsigned a[2][4];
#pragma unroll
            for (int mr = 0; mr < 2; ++mr) {
                unsigned aaddr = smem_u32(&As[(wy * 32 + mr * 16 + (lane & 15)) * GA_STRIDE
                                              + kk * 16 + (lane >> 4) * 8]);
                ldsm_x4(a[mr][0], a[mr][1], a[mr][2], a[mr][3], aaddr);
            }
#pragma unroll
            for (int nc = 0; nc < 4; ++nc) {
                unsigned q0, q1, q2, q3;
                unsigned baddr = smem_u32(&Bs[(kk * 16 + (lane & 15)) * GB_STRIDE
                                              + wx * 64 + nc * 16 + (lane >> 4) * 8]);
                ldsm_x4_t(q0, q1, q2, q3, baddr);
#pragma unroll
                for (int mr = 0; mr < 2; ++mr) {
                    mma16816(c[mr][nc * 2],     a[mr][0], a[mr][1], a[mr][2], a[mr][3], q0, q1);
                    mma16816(c[mr][nc * 2 + 1], a[mr][0], a[mr][1], a[mr][2], a[mr][3], q2, q3);
                }
            }
        }
        // issue next-next stage AFTER compute: writes buffer (it+2)%3, which no
        // warp can be reading (readers use it%3 / (it+1)%3)
        if (it + 2 < niter) load_stage(it + 2);
    }
    __syncthreads();   // all compute done before Stage aliases the buffers

    // epilogue: bias -> fp16 -> smem stage -> coalesced uint4 stores (active rows)
    const int r = lane >> 2;
    const int cb2 = (lane & 3) * 2;
#pragma unroll
    for (int mr = 0; mr < 2; ++mr) {
#pragma unroll
        for (int nc2 = 0; nc2 < 8; ++nc2) {
            int col = wx * 64 + nc2 * 8 + cb2;
            float bx = bias[nb + col];
            float by = bias[nb + col + 1];
            int row = wy * 32 + mr * 16 + r;
            __half2 lo = __floats2half2_rn(c[mr][nc2][0] + bx, c[mr][nc2][1] + by);
            __half2 hi = __floats2half2_rn(c[mr][nc2][2] + bx, c[mr][nc2][3] + by);
            *(__half2*)&Stage[row * GB_STRIDE + col]       = lo;
            *(__half2*)&Stage[(row + 8) * GB_STRIDE + col] = hi;
        }
    }
    __syncthreads();
#pragma unroll
    for (int j = 0; j < 8; ++j) {
        int idx = tid + j * 256;
        int row = idx >> 4;
        int colc = (idx & 15) * 8;
        if (actf[row]) {
            *(uint4*)&g_xpre16[(size_t)(m0 + row) * 1024 + nb + colc] =
                *(const uint4*)&Stage[row * GB_STRIDE + colc];
        }
    }
}

// ---------------------------------------------------------------------------
// Persistent recurrent kernel v6 — in-register gate handoff + coalesced xpre.
// ---------------------------------------------------------------------------
#define WH_STRIDE 520
#define HS_STRIDE 136
#define HS_BUFSZ  (16 * HS_STRIDE)
#define SM_HS_OFF 133120
#define SM_LS_OFF (SM_HS_OFF + 2 * HS_BUFSZ * 2)
#define REC_SMEM  (SM_LS_OFF + 128)

__global__ __launch_bounds__(512) void rec_mma(const int* __restrict__ seq_len, int layer)
{
    extern __shared__ char smraw[];
    __half* WH = (__half*)(smraw);
    __half* HS = (__half*)(smraw + SM_HS_OFF);
    int*    LS = (int*)(smraw + SM_LS_OFF);

    const int blk = blockIdx.x;
    const int dir = blk >> 6;
    const int b0 = (blk & 63) * 16;
    const int xoff = dir * 512;
    const int ooff = dir * 128;
    const int tid = threadIdx.x;

    __half* outh = (layer == 0) ? g_cur0h : g_cur1h;

    const __half* wg = g_wh16 + (size_t)(layer * 2 + dir) * 65536;
#pragma unroll 4
    for (int i = tid; i < 8192; i += 512) {
        int r = i >> 6;
        int c8 = i & 63;
        *(uint4*)&WH[r * WH_STRIDE + c8 * 8] = ((const uint4*)wg)[i];
    }
    for (int i = tid; i < HS_BUFSZ; i += 512) { ((unsigned*)HS)[i] = 0u; }
    if (tid < 16) LS[tid] = seq_len[b0 + tid];
    __syncthreads();
    if (tid == 0) {
        int m = 0;
#pragma unroll
        for (int i = 0; i < 16; ++i) m = max(m, LS[i]);
        LS[16] = m;
    }
    __syncthreads();
    const int Lmax = LS[16];

    const int warp = tid >> 5;
    const int lane = tid & 31;
    const int n_base = warp * 32;
    const int arow = lane & 15;
    const int acol8 = (lane >> 4) * 8;

    unsigned bfr[8][8];
#pragma unroll
    for (int kk = 0; kk < 8; ++kk) {
#pragma unroll
        for (int nt2 = 0; nt2 < 2; ++nt2) {
            unsigned baddr = smem_u32(&WH[(kk * 16 + arow) * WH_STRIDE + n_base + nt2 * 16 + acol8]);
            ldsm_x4_t(bfr[kk][nt2 * 4 + 0], bfr[kk][nt2 * 4 + 1],
                      bfr[kk][nt2 * 4 + 2], bfr[kk][nt2 * 4 + 3], baddr);
        }
    }

    const int rr = lane >> 2;
    const int cb = (lane & 3) * 2;
    const int hp = warp * 8 + cb;
    const int xcol = xoff + warp * 32 + (cb >> 1) * 8;
    const int L0 = LS[rr];
    const int L1 = LS[rr + 8];
    const size_t bR0 = (size_t)(b0 + rr);
    const size_t bR1 = (size_t)(b0 + rr + 8);

    float c_reg[4] = {0.f, 0.f, 0.f, 0.f};

    for (int step = 0; step < Lmax; ++step) {
        const bool act0 = (step < L0);
        const bool act1 = (step < L1);
        const int idx0 = act0 ? (dir ? (L0 - 1 - step) : step) : step;
        const int idx1 = act1 ? (dir ? (L1 - 1 - step) : step) : step;

        uint4 xv0 = make_uint4(0u, 0u, 0u, 0u);
        uint4 xv1 = make_uint4(0u, 0u, 0u, 0u);
        if (act0) xv0 = *(const uint4*)(g_xpre16 + (bR0 * TT + idx0) * 1024 + xcol);
        if (act1) xv1 = *(const uint4*)(g_xpre16 + (bR1 * TT + idx1) * 1024 + xcol);

        float c[4][4];
#pragma unroll
        for (int i = 0; i < 4; ++i) {
#pragma unroll
            for (int j = 0; j < 4; ++j) c[i][j] = 0.f;
        }
        {
            const __half* hsrc = HS + (step & 1) * HS_BUFSZ;
#pragma unroll
            for (int kk = 0; kk < 8; ++kk) {
                unsigned a0, a1, a2, a3;
                unsigned aaddr = smem_u32(&hsrc[arow * HS_STRIDE + kk * 16 + acol8]);
                ldsm_x4(a0, a1, a2, a3, aaddr);
                mma16816(c[0], a0, a1, a2, a3, bfr[kk][0], bfr[kk][1]);
                mma16816(c[1], a0, a1, a2, a3, bfr[kk][2], bfr[kk][3]);
                mma16816(c[2], a0, a1, a2, a3, bfr[kk][4], bfr[kk][5]);
                mma16816(c[3], a0, a1, a2, a3, bfr[kk][6], bfr[kk][7]);
            }
        }

        __half* hdst = HS + ((step + 1) & 1) * HS_BUFSZ;

        {   // row rr
            float2 xi = __half22float2(*(__half2*)&xv0.x);
            float2 xj = __half22float2(*(__half2*)&xv0.y);
            float2 xf = __half22float2(*(__half2*)&xv0.z);
            float2 xo = __half22float2(*(__half2*)&xv0.w);
            float hv0 = 0.f, hv1 = 0.f;
            if (act0) {
                float gi0 = c[0][0] + xi.x, gi1 = c[0][1] + xi.y;
                float gj0 = c[1][0] + xj.x, gj1 = c[1][1] + xj.y;
                float gf0 = c[2][0] + xf.x + 1.f, gf1 = c[2][1] + xf.y + 1.f;
                float go0 = c[3][0] + xo.x, go1 = c[3][1] + xo.y;
                float cn0 = fmaf(c_reg[0], sig_apx(gf0), sig_apx(gi0) * tanh_apx(gj0));
                float cn1 = fmaf(c_reg[1], sig_apx(gf1), sig_apx(gi1) * tanh_apx(gj1));
                c_reg[0] = cn0; c_reg[1] = cn1;
                hv0 = tanh_apx(cn0) * sig_apx(go0);
                hv1 = tanh_apx(cn1) * sig_apx(go1);
            }
            __half2 hb = __floats2half2_rn(hv0, hv1);
            *(__half2*)&outh[(bR0 * TT + idx0) * 256 + ooff + hp] = hb;
            if (act0) *(__half2*)&hdst[rr * HS_STRIDE + hp] = hb;
        }
        {   // row rr+8
            float2 xi = __half22float2(*(__half2*)&xv1.x);
            float2 xj = __half22float2(*(__half2*)&xv1.y);
            float2 xf = __half22float2(*(__half2*)&xv1.z);
            float2 xo = __half22float2(*(__half2*)&xv1.w);
            float hv0 = 0.f, hv1 = 0.f;
            if (act1) {
                float gi0 = c[0][2] + xi.x, gi1 = c[0][3] + xi.y;
                float gj0 = c[1][2] + xj.x, gj1 = c[1][3] + xj.y;
                float gf0 = c[2][2] + xf.x + 1.f, gf1 = c[2][3] + xf.y + 1.f;
                float go0 = c[3][2] + xo.x, go1 = c[3][3] + xo.y;
                float cn0 = fmaf(c_reg[2], sig_apx(gf0), sig_apx(gi0) * tanh_apx(gj0));
                float cn1 = fmaf(c_reg[3], sig_apx(gf1), sig_apx(gi1) * tanh_apx(gj1));
                c_reg[2] = cn0; c_reg[3] = cn1;
                hv0 = tanh_apx(cn0) * sig_apx(go0);
                hv1 = tanh_apx(cn1) * sig_apx(go1);
            }
            __half2 hb = __floats2half2_rn(hv0, hv1);
            *(__half2*)&outh[(bR1 * TT + idx1) * 256 + ooff + hp] = hb;
            if (act1) *(__half2*)&hdst[(rr + 8) * HS_STRIDE + hp] = hb;
        }

        __syncthreads();
    }

    for (int step = Lmax; step < TT; ++step) {
        *(unsigned*)&outh[(bR0 * TT + step) * 256 + ooff + hp] = 0u;
        *(unsigned*)&outh[(bR1 * TT + step) * 256 + ooff + hp] = 0u;
    }
}

// ---------------------------------------------------------------------------
// Attention pooling (single pass, smem-resident tile): g_cur1h -> g_attb
// ---------------------------------------------------------------------------
#define ATT_TILE_BYTES (TT * 256 * 2)
#define ATT_WV_OFF  ATT_TILE_BYTES
#define ATT_E_OFF   (ATT_WV_OFF + 256 * 4)
#define ATT_RED_OFF (ATT_E_OFF + 176 * 4)
#define ATT_SMEM    (ATT_RED_OFF + 40 * 4)

__global__ __launch_bounds__(256) void att_kernel(
    const float* __restrict__ w_att, const float* __restrict__ b_att)
{
    extern __shared__ char asm_raw[];
    __half* tile = (__half*)(asm_raw);
    float*  wv   = (float*)(asm_raw + ATT_WV_OFF);
    float*  e_sm = (float*)(asm_raw + ATT_E_OFF);
    float*  red  = (float*)(asm_raw + ATT_RED_OFF);

    const int b = blockIdx.x;
    const int tid = threadIdx.x;
    wv[tid] = w_att[tid];

    const uint4* src = (const uint4*)&g_cur1h[(size_t)b * TT * 256];
    for (int i = tid; i < TT * 256 / 8; i += 256) {
        ((uint4*)tile)[i] = src[i];
    }
    __syncthreads();

    const int warp = tid >> 5;
    const int lane = tid & 31;

    for (int t = warp; t < TT; t += 8) {
        const __half* p = &tile[t * 256 + lane * 8];
        float s = 0.f;
#pragma unroll
        for (int j = 0; j < 4; ++j) {
            __half2 hh = *(const __half2*)(p + j * 2);
            float2 ff = __half22float2(hh);
            s += ff.x * wv[lane * 8 + j * 2] + ff.y * wv[lane * 8 + j * 2 + 1];
        }
#pragma unroll
        for (int off = 16; off > 0; off >>= 1) s += __shfl_down_sync(0xffffffffu, s, off);
        if (lane == 0) e_sm[t] = tanhf(s + b_att[0]);
    }
    __syncthreads();

    float m = -1e30f;
    for (int t = tid; t < TT; t += 256) m = fmaxf(m, e_sm[t]);
#pragma unroll
    for (int off = 16; off > 0; off >>= 1) m = fmaxf(m, __shfl_xor_sync(0xffffffffu, m, off));
    if (lane == 0) red[warp] = m;
    __syncthreads();
    if (tid == 0) {
        float mm = red[0];
        for (int w = 1; w < 8; ++w) mm = fmaxf(mm, red[w]);
        red[32] = mm;
    }
    __syncthreads();
    const float mx = red[32];

    float ssum = 0.f;
    for (int t = tid; t < TT; t += 256) {
        float p = expf(e_sm[t] - mx);
        e_sm[t] = p;
        ssum += p;
    }
#pragma unroll
    for (int off = 16; off > 0; off >>= 1) ssum += __shfl_xor_sync(0xffffffffu, ssum, off);
    if (lane == 0) red[warp] = ssum;
    __syncthreads();
    if (tid == 0) {
        float s2 = 0.f;
        for (int w = 0; w < 8; ++w) s2 += red[w];
        red[33] = s2;
    }
    __syncthreads();
    const float inv = 1.f / red[33];

    float acc = 0.f;
    const __half* base = &tile[tid];
    for (int t = 0; t < TT; ++t) {
        acc += e_sm[t] * __half2float(base[t * 256]);
    }
    g_attb[b * 256 + tid] = acc * inv;
}

// ---------------------------------------------------------------------------
// Classifier head: [g_sbuf, g_attb] -> out
// ---------------------------------------------------------------------------
__global__ __launch_bounds__(64) void head_kernel(
    const float* __restrict__ w1, const float* __restrict__ b1,
    const float* __restrict__ w2, const float* __restrict__ b2,
    float* __restrict__ out)
{
    const int b = blockIdx.x;
    const int tid = threadIdx.x;
    __shared__ float cat[272];
    __shared__ float h1[64];
    if (tid < 16) cat[tid] = g_sbuf[b * 16 + tid];
    for (int j = tid; j < 256; j += 64) cat[16 + j] = g_attb[b * 256 + j];
    __syncthreads();
    float a = b1[tid];
#pragma unroll 4
    for (int k = 0; k < 272; ++k) a += cat[k] * w1[k * 64 + tid];
    h1[tid] = fmaxf(a, 0.f);
    __syncthreads();
    if (tid < 32) {
        float a2 = b2[tid];
#pragma unroll
        for (int k = 0; k < 64; ++k) a2 += h1[k] * w2[k * 32 + tid];
        out[b * 32 + tid] = fmaxf(a2, 0.f);
    }
}

// ---------------------------------------------------------------------------
// Launch
// ---------------------------------------------------------------------------
extern "C" void kernel_launch(void* const* d_in, const int* in_sizes, int n_in,
                              void* d_out, int out_size)
{
    const float* x_static = (const float*)d_in[0];
    const float* x_dyn    = (const float*)d_in[1];
    const int*   seq      = (const int*)  d_in[2];
    const float* w_s0  = (const float*)d_in[3];
    const float* b_s0  = (const float*)d_in[4];
    const float* w_s1  = (const float*)d_in[5];
    const float* b_s1  = (const float*)d_in[6];
    const float* Wx_f0 = (const float*)d_in[7];
    const float* Wh_f0 = (const float*)d_in[8];
    const float* bb_f0 = (const float*)d_in[9];
    const float* Wx_b0 = (const float*)d_in[10];
    const float* Wh_b0 = (const float*)d_in[11];
    const float* bb_b0 = (const float*)d_in[12];
    const float* Wx_f1 = (const float*)d_in[13];
    const float* Wh_f1 = (const float*)d_in[14];
    const float* bb_f1 = (const float*)d_in[15];
    const float* Wx_b1 = (const float*)d_in[16];
    const float* Wh_b1 = (const float*)d_in[17];
    const float* bb_b1 = (const float*)d_in[18];
    const float* w_att = (const float*)d_in[19];
    const float* b_att = (const float*)d_in[20];
    const float* w_c1  = (const float*)d_in[21];
    const float* b_c1  = (const float*)d_in[22];
    const float* w_c2  = (const float*)d_in[23];
    const float* b_c2  = (const float*)d_in[24];
    float* out = (float*)d_out;

    cudaFuncSetAttribute(rec_mma, cudaFuncAttributeMaxDynamicSharedMemorySize, REC_SMEM);
    cudaFuncSetAttribute(att_kernel, cudaFuncAttributeMaxDynamicSharedMemorySize, ATT_SMEM);
    cudaFuncSetAttribute(xpre_gemm2, cudaFuncAttributeMaxDynamicSharedMemorySize, GEMM_SMEM);

    // launch order chosen so the harness's ncu window (-s 5 -c 1) captures gemm1
    prep_wh<<<128, 256>>>(Wh_f0, Wh_b0, Wh_f1, Wh_b1);
    prep_wx<<<128, 256>>>(Wx_f0, Wx_b0, Wx_f1, Wx_b1, bb_f0, bb_b0, bb_f1, bb_b1);
    static_kernel<<<(BATCH + 255) / 256, 256>>>(x_static, w_s0, b_s0, w_s1, b_s1);

    dim3 ggrid(8, MTOT / 128);
    xpre_gemm2<<<ggrid, 256, GEMM_SMEM>>>(x_dyn, FDYN, 0, seq);
    rec_mma<<<128, 512, REC_SMEM>>>(seq, 0);
    xpre_gemm2<<<ggrid, 256, GEMM_SMEM>>>(nullptr, 256, 1, seq);
    rec_mma<<<128, 512, REC_SMEM>>>(seq, 1);
    att_kernel<<<BATCH, 256, ATT_SMEM>>>(w_att, b_att);
    head_kernel<<<BATCH, 64>>>(w_c1, b_c1, w_c2, b_c2, out);
}